// round 1
// baseline (speedup 1.0000x reference)
#include <cuda_runtime.h>
#include <cuda_bf16.h>
#include <math.h>

// Problem constants
#define T_LEN 2048
#define BATCH 2
#define EMBED 1024
#define NHEAD 16
#define HDIM  64
#define BHEAD (BATCH * NHEAD)          // 32
#define NTOK  (T_LEN * BATCH)          // 4096
#define SCALING 0.125f                  // 64^-0.5

// Scratch (allocation-free rule: __device__ globals)
__device__ float g_q[BHEAD * T_LEN * HDIM];     // [bh][t][d], pre-scaled
__device__ float g_k[BHEAD * T_LEN * HDIM];
__device__ float g_v[BHEAD * T_LEN * HDIM];
__device__ float g_ctx[NTOK * EMBED];           // [t*2+b][e] attention output

// ---------------------------------------------------------------------------
// Kernel 1: QKV projection.  C[n,f] = dot(x[n,:], W[f,:]) + bias[f]
// n in [0,4096), f in [0,3072).  Epilogue scatters to g_q/g_k/g_v with q scaling.
// 128x128 block tile, BK=8, 256 threads, 8x8 per thread (2x2 split of 4x4).
// ---------------------------------------------------------------------------
__global__ __launch_bounds__(256) void qkv_kernel(
    const float* __restrict__ x,      // [4096,1024]
    const float* __restrict__ w,      // [3072,1024]
    const float* __restrict__ bias)   // [3072]
{
    __shared__ float As[8][128];   // [k][m]
    __shared__ float Bs[8][128];   // [k][n]

    const int bm = blockIdx.y * 128;
    const int bn = blockIdx.x * 128;
    const int tid = threadIdx.x;
    const int tx = tid & 15;       // 0..15 -> n
    const int ty = tid >> 4;       // 0..15 -> m

    float acc[2][2][4][4];
    #pragma unroll
    for (int a = 0; a < 2; a++)
        #pragma unroll
        for (int b = 0; b < 2; b++)
            #pragma unroll
            for (int i = 0; i < 4; i++)
                #pragma unroll
                for (int j = 0; j < 4; j++) acc[a][b][i][j] = 0.f;

    const int lr = tid >> 1;            // 0..127 row within tile
    const int lc = (tid & 1) * 4;       // 0 or 4
    const float* aptr = x + (size_t)(bm + lr) * EMBED + lc;
    const float* bptr = w + (size_t)(bn + lr) * EMBED + lc;

    for (int k0 = 0; k0 < EMBED; k0 += 8) {
        float4 av = *(const float4*)(aptr + k0);
        float4 bv = *(const float4*)(bptr + k0);
        As[lc + 0][lr] = av.x; As[lc + 1][lr] = av.y;
        As[lc + 2][lr] = av.z; As[lc + 3][lr] = av.w;
        Bs[lc + 0][lr] = bv.x; Bs[lc + 1][lr] = bv.y;
        Bs[lc + 2][lr] = bv.z; Bs[lc + 3][lr] = bv.w;
        __syncthreads();
        #pragma unroll
        for (int kk = 0; kk < 8; kk++) {
            float4 a0 = *(const float4*)&As[kk][ty * 4];
            float4 a1 = *(const float4*)&As[kk][ty * 4 + 64];
            float4 b0 = *(const float4*)&Bs[kk][tx * 4];
            float4 b1 = *(const float4*)&Bs[kk][tx * 4 + 64];
            float ar[2][4] = {{a0.x, a0.y, a0.z, a0.w}, {a1.x, a1.y, a1.z, a1.w}};
            float br[2][4] = {{b0.x, b0.y, b0.z, b0.w}, {b1.x, b1.y, b1.z, b1.w}};
            #pragma unroll
            for (int im = 0; im < 2; im++)
                #pragma unroll
                for (int in2 = 0; in2 < 2; in2++)
                    #pragma unroll
                    for (int i = 0; i < 4; i++)
                        #pragma unroll
                        for (int j = 0; j < 4; j++)
                            acc[im][in2][i][j] = fmaf(ar[im][i], br[in2][j], acc[im][in2][i][j]);
        }
        __syncthreads();
    }

    // Epilogue: bias, q-scaling, scatter to [bh][t][d]
    #pragma unroll
    for (int im = 0; im < 2; im++) {
        #pragma unroll
        for (int i = 0; i < 4; i++) {
            int m = bm + im * 64 + ty * 4 + i;        // token row
            int t = m >> 1;
            int b = m & 1;
            #pragma unroll
            for (int in2 = 0; in2 < 2; in2++) {
                #pragma unroll
                for (int j = 0; j < 4; j++) {
                    int f = bn + in2 * 64 + tx * 4 + j;
                    float c = acc[im][in2][i][j] + bias[f];
                    int which = f >> 10;        // 0=q,1=k,2=v
                    int hd = f & 1023;
                    int h = hd >> 6;
                    int d = hd & 63;
                    if (which == 0) c *= SCALING;
                    float* dst = (which == 0) ? g_q : (which == 1) ? g_k : g_v;
                    dst[(((size_t)(b * NHEAD + h)) * T_LEN + t) * HDIM + d] = c;
                }
            }
        }
    }
}

// ---------------------------------------------------------------------------
// Kernel 2: flash attention, fp32.  One block = (bh, 64-query tile).
// Smem layouts chosen so all inner-loop reads are conflict-free LDS.128:
//   Qs[k][r], Ks[k][c], Vs[s][d], Ps[c][r]  (all padded to 68 floats/row)
// ---------------------------------------------------------------------------
#define PADW 68
#define ATTN_SMEM ((4 * 64 * PADW + 3 * 64) * (int)sizeof(float))

__global__ __launch_bounds__(256) void attn_kernel()
{
    extern __shared__ float sm[];
    float* Qs = sm;                    // [64][68] transposed: [k][r]
    float* Ks = Qs + 64 * PADW;        // [64][68] transposed: [k][c]
    float* Vs = Ks + 64 * PADW;        // [64][68] natural:    [s][d]
    float* Ps = Vs + 64 * PADW;        // [64][68] transposed: [c][r]
    float* sm_m = Ps + 64 * PADW;      // [64] running row max
    float* sm_a = sm_m + 64;           // [64] rescale alpha
    float* sm_l = sm_a + 64;           // [64] 1/l at end

    const int bh = blockIdx.y;
    const int q0 = blockIdx.x * 64;
    const int tid = threadIdx.x;
    const int tx = tid & 15;           // -> col group (keys / dims)
    const int ty = tid >> 4;           // -> row group (queries)

    const float* qptr = g_q + (size_t)bh * T_LEN * HDIM;
    const float* kptr = g_k + (size_t)bh * T_LEN * HDIM;
    const float* vptr = g_v + (size_t)bh * T_LEN * HDIM;

    // Load Q tile transposed
    #pragma unroll
    for (int it = 0; it < 4; it++) {
        int idx = tid + it * 256;      // float4 index, 1024 total
        int r = idx >> 4;
        int c4 = (idx & 15) * 4;
        float4 qv = *(const float4*)(qptr + (size_t)(q0 + r) * HDIM + c4);
        Qs[(c4 + 0) * PADW + r] = qv.x;
        Qs[(c4 + 1) * PADW + r] = qv.y;
        Qs[(c4 + 2) * PADW + r] = qv.z;
        Qs[(c4 + 3) * PADW + r] = qv.w;
    }

    float m_i = -1e30f, l_i = 0.f;     // valid for tid<64 (row = tid)
    float accO[4][4];
    #pragma unroll
    for (int i = 0; i < 4; i++)
        #pragma unroll
        for (int j = 0; j < 4; j++) accO[i][j] = 0.f;

    for (int s0 = 0; s0 < T_LEN; s0 += 64) {
        // Load K (transposed) and V (natural)
        #pragma unroll
        for (int it = 0; it < 4; it++) {
            int idx = tid + it * 256;
            int r = idx >> 4;
            int c4 = (idx & 15) * 4;
            float4 kv = *(const float4*)(kptr + (size_t)(s0 + r) * HDIM + c4);
            Ks[(c4 + 0) * PADW + r] = kv.x;
            Ks[(c4 + 1) * PADW + r] = kv.y;
            Ks[(c4 + 2) * PADW + r] = kv.z;
            Ks[(c4 + 3) * PADW + r] = kv.w;
            float4 vv = *(const float4*)(vptr + (size_t)(s0 + r) * HDIM + c4);
            *(float4*)(Vs + r * PADW + c4) = vv;
        }
        __syncthreads();

        // S = Q K^T  (thread owns rows ty*4+i, cols tx*4+j)
        float accS[4][4];
        #pragma unroll
        for (int i = 0; i < 4; i++)
            #pragma unroll
            for (int j = 0; j < 4; j++) accS[i][j] = 0.f;
        #pragma unroll 8
        for (int kk = 0; kk < 64; kk++) {
            float4 qa = *(const float4*)(Qs + kk * PADW + ty * 4);
            float4 kb = *(const float4*)(Ks + kk * PADW + tx * 4);
            float qr[4] = {qa.x, qa.y, qa.z, qa.w};
            float kr[4] = {kb.x, kb.y, kb.z, kb.w};
            #pragma unroll
            for (int i = 0; i < 4; i++)
                #pragma unroll
                for (int j = 0; j < 4; j++)
                    accS[i][j] = fmaf(qr[i], kr[j], accS[i][j]);
        }

        // Stage raw S (transposed) for row-max
        #pragma unroll
        for (int i = 0; i < 4; i++)
            #pragma unroll
            for (int j = 0; j < 4; j++)
                Ps[(tx * 4 + j) * PADW + (ty * 4 + i)] = accS[i][j];
        __syncthreads();

        if (tid < 64) {
            float mx = -1e30f;
            #pragma unroll 8
            for (int c = 0; c < 64; c++) mx = fmaxf(mx, Ps[c * PADW + tid]);
            float m_new = fmaxf(m_i, mx);
            sm_a[tid] = __expf(m_i - m_new);
            sm_m[tid] = m_new;
            m_i = m_new;
        }
        __syncthreads();

        // exp + O rescale (uses register copy of S)
        float alpha[4], mrow[4];
        #pragma unroll
        for (int i = 0; i < 4; i++) { alpha[i] = sm_a[ty * 4 + i]; mrow[i] = sm_m[ty * 4 + i]; }
        #pragma unroll
        for (int i = 0; i < 4; i++)
            #pragma unroll
            for (int j = 0; j < 4; j++) {
                float p = __expf(accS[i][j] - mrow[i]);
                Ps[(tx * 4 + j) * PADW + (ty * 4 + i)] = p;
                accO[i][j] *= alpha[i];
            }
        __syncthreads();

        // row-sum for l (tid<64) — concurrent with PV (both only read Ps)
        if (tid < 64) {
            float s = 0.f;
            #pragma unroll 8
            for (int c = 0; c < 64; c++) s += Ps[c * PADW + tid];
            l_i = l_i * sm_a[tid] + s;
        }

        // O += P V   (Ps is [s][r] transposed, Vs is [s][d])
        #pragma unroll 8
        for (int ss = 0; ss < 64; ss++) {
            float4 pa = *(const float4*)(Ps + ss * PADW + ty * 4);
            float4 vb = *(const float4*)(Vs + ss * PADW + tx * 4);
            float pr[4] = {pa.x, pa.y, pa.z, pa.w};
            float vr[4] = {vb.x, vb.y, vb.z, vb.w};
            #pragma unroll
            for (int i = 0; i < 4; i++)
                #pragma unroll
                for (int j = 0; j < 4; j++)
                    accO[i][j] = fmaf(pr[i], vr[j], accO[i][j]);
        }
        __syncthreads();   // protect smem before next tile load
    }

    if (tid < 64) sm_l[tid] = 1.0f / l_i;
    __syncthreads();

    // Write ctx[t*2+b][h*64+d]
    const int b = bh >> 4;
    const int h = bh & 15;
    #pragma unroll
    for (int i = 0; i < 4; i++) {
        int t = q0 + ty * 4 + i;
        float inv = sm_l[ty * 4 + i];
        float4 o;
        o.x = accO[i][0] * inv;
        o.y = accO[i][1] * inv;
        o.z = accO[i][2] * inv;
        o.w = accO[i][3] * inv;
        *(float4*)(g_ctx + ((size_t)t * BATCH + b) * EMBED + h * HDIM + tx * 4) = o;
    }
}

// ---------------------------------------------------------------------------
// Kernel 3: output projection.  out[n,f] = dot(ctx[n,:], Wo[f,:]) + bias[f]
// Same sgemm core as kernel 1.
// ---------------------------------------------------------------------------
__global__ __launch_bounds__(256) void outproj_kernel(
    const float* __restrict__ w,      // [1024,1024]
    const float* __restrict__ bias,   // [1024]
    float* __restrict__ out)          // [4096,1024]
{
    __shared__ float As[8][128];
    __shared__ float Bs[8][128];

    const int bm = blockIdx.y * 128;
    const int bn = blockIdx.x * 128;
    const int tid = threadIdx.x;
    const int tx = tid & 15;
    const int ty = tid >> 4;

    float acc[2][2][4][4];
    #pragma unroll
    for (int a = 0; a < 2; a++)
        #pragma unroll
        for (int b = 0; b < 2; b++)
            #pragma unroll
            for (int i = 0; i < 4; i++)
                #pragma unroll
                for (int j = 0; j < 4; j++) acc[a][b][i][j] = 0.f;

    const int lr = tid >> 1;
    const int lc = (tid & 1) * 4;
    const float* aptr = g_ctx + (size_t)(bm + lr) * EMBED + lc;
    const float* bptr = w + (size_t)(bn + lr) * EMBED + lc;

    for (int k0 = 0; k0 < EMBED; k0 += 8) {
        float4 av = *(const float4*)(aptr + k0);
        float4 bv = *(const float4*)(bptr + k0);
        As[lc + 0][lr] = av.x; As[lc + 1][lr] = av.y;
        As[lc + 2][lr] = av.z; As[lc + 3][lr] = av.w;
        Bs[lc + 0][lr] = bv.x; Bs[lc + 1][lr] = bv.y;
        Bs[lc + 2][lr] = bv.z; Bs[lc + 3][lr] = bv.w;
        __syncthreads();
        #pragma unroll
        for (int kk = 0; kk < 8; kk++) {
            float4 a0 = *(const float4*)&As[kk][ty * 4];
            float4 a1 = *(const float4*)&As[kk][ty * 4 + 64];
            float4 b0 = *(const float4*)&Bs[kk][tx * 4];
            float4 b1 = *(const float4*)&Bs[kk][tx * 4 + 64];
            float ar[2][4] = {{a0.x, a0.y, a0.z, a0.w}, {a1.x, a1.y, a1.z, a1.w}};
            float br[2][4] = {{b0.x, b0.y, b0.z, b0.w}, {b1.x, b1.y, b1.z, b1.w}};
            #pragma unroll
            for (int im = 0; im < 2; im++)
                #pragma unroll
                for (int in2 = 0; in2 < 2; in2++)
                    #pragma unroll
                    for (int i = 0; i < 4; i++)
                        #pragma unroll
                        for (int j = 0; j < 4; j++)
                            acc[im][in2][i][j] = fmaf(ar[im][i], br[in2][j], acc[im][in2][i][j]);
        }
        __syncthreads();
    }

    #pragma unroll
    for (int im = 0; im < 2; im++)
        #pragma unroll
        for (int i = 0; i < 4; i++) {
            int m = bm + im * 64 + ty * 4 + i;
            #pragma unroll
            for (int in2 = 0; in2 < 2; in2++)
                #pragma unroll
                for (int j = 0; j < 4; j++) {
                    int f = bn + in2 * 64 + tx * 4 + j;
                    out[(size_t)m * EMBED + f] = acc[im][in2][i][j] + bias[f];
                }
        }
}

// ---------------------------------------------------------------------------
extern "C" void kernel_launch(void* const* d_in, const int* in_sizes, int n_in,
                              void* d_out, int out_size)
{
    const float* x  = (const float*)d_in[0];   // [2048,2,1024]
    const float* w1 = (const float*)d_in[1];   // [3072,1024]
    const float* b1 = (const float*)d_in[2];   // [3072]
    const float* w2 = (const float*)d_in[3];   // [1024,1024]
    const float* b2 = (const float*)d_in[4];   // [1024]
    float* out = (float*)d_out;

    static bool attr_set = false;
    if (!attr_set) {
        cudaFuncSetAttribute(attn_kernel,
                             cudaFuncAttributeMaxDynamicSharedMemorySize, ATTN_SMEM);
        attr_set = true;
    }

    qkv_kernel<<<dim3(24, 32), 256>>>(x, w1, b1);
    attn_kernel<<<dim3(T_LEN / 64, BHEAD), 256, ATTN_SMEM>>>();
    outproj_kernel<<<dim3(8, 32), 256>>>(w2, b2, out);
}